// round 11
// baseline (speedup 1.0000x reference)
#include <cuda_runtime.h>
#include <cuda_bf16.h>
#include <cuda_fp16.h>
#include <math.h>
#include <stdint.h>

#define NN 32768
#define NE 524288
#define FTIN 256
#define HID 128
#define NB 64
#define EPSV 1e-7f

// ---------------- scratch (static device globals; no allocation) ----------------
__device__ __align__(16) uint16_t g_Uhi[NN * FTIN];
__device__ __align__(16) uint16_t g_Ulo[NN * FTIN];
__device__ __align__(16) __half   g_Zh [NN * HID];      // z in fp16 (gather payload)
__device__ __align__(16) float    g_H2 [NN * (HID + 1)];
__device__ __align__(16) float    g_part[512 * 129];    // head partial sums
__device__ __align__(16) uint16_t g_W1hiT[HID * FTIN];  // [n][k] bf16
__device__ __align__(16) uint16_t g_W1loT[HID * FTIN];
__device__ __align__(16) uint16_t g_W2hiT[HID * HID];
__device__ __align__(16) uint16_t g_W2loT[HID * HID];
__device__ float g_ssrc[NN];
__device__ float g_sdst[NN];
__device__ int   g_cnt[NN];
__device__ int   g_rowstart[NN + 1];
__device__ int   g_work[NN];
__device__ int   g_csrsrc[NE];

// ---------------- helpers ----------------
__device__ __forceinline__ float warp_sum(float v) {
#pragma unroll
    for (int o = 16; o; o >>= 1) v += __shfl_xor_sync(0xffffffffu, v, o);
    return v;
}
__device__ __forceinline__ float warp_max(float v) {
#pragma unroll
    for (int o = 16; o; o >>= 1) v = fmaxf(v, __shfl_xor_sync(0xffffffffu, v, o));
    return v;
}
__device__ __forceinline__ float gelu_tanh(float x) {
    float x3 = x * x * x;
    return 0.5f * x * (1.0f + tanhf(0.7978845608028654f * (x + 0.044715f * x3)));
}
__device__ __forceinline__ float lrelu02(float x) { return x < 0.0f ? 0.2f * x : x; }

__device__ __forceinline__ void mma_bf16(float* d, uint32_t a0, uint32_t a1, uint32_t a2,
                                         uint32_t a3, uint32_t b0, uint32_t b1) {
    asm volatile(
        "mma.sync.aligned.m16n8k16.row.col.f32.bf16.bf16.f32 "
        "{%0,%1,%2,%3}, {%4,%5,%6,%7}, {%8,%9}, {%0,%1,%2,%3};"
        : "+f"(d[0]), "+f"(d[1]), "+f"(d[2]), "+f"(d[3])
        : "r"(a0), "r"(a1), "r"(a2), "r"(a3), "r"(b0), "r"(b1));
}

// ---------------- CSR build ----------------
__global__ void k_zero_cnt() {
    int i = blockIdx.x * blockDim.x + threadIdx.x;
    if (i < NN) g_cnt[i] = 0;
}
__global__ void k_hist(const int* __restrict__ ei, int ne) {
    int e = blockIdx.x * blockDim.x + threadIdx.x;
    if (e < ne) atomicAdd(&g_cnt[ei[e]], 1);
}
__global__ void k_scan() {
    __shared__ int part[1024];
    int t = threadIdx.x;
    int base = t * 32;
    int s = 0;
    for (int i = 0; i < 32; i++) s += g_cnt[base + i];
    part[t] = s;
    __syncthreads();
    for (int off = 1; off < 1024; off <<= 1) {
        int v = 0;
        if (t >= off) v = part[t - off];
        __syncthreads();
        if (t >= off) part[t] += v;
        __syncthreads();
    }
    int run = (t == 0) ? 0 : part[t - 1];
    for (int i = 0; i < 32; i++) {
        int c = g_cnt[base + i];
        g_rowstart[base + i] = run;
        g_work[base + i] = run;
        run += c;
    }
    if (t == 1023) g_rowstart[NN] = run;
}
__global__ void k_scatter(const int* __restrict__ ei, int ne) {
    int e = blockIdx.x * blockDim.x + threadIdx.x;
    if (e < ne) {
        int d = ei[e];
        int s = ei[NE + e];
        int pos = atomicAdd(&g_work[d], 1);
        g_csrsrc[pos] = s;
    }
}

// -------- logmap0 of raw x (257 -> 256), emitting bf16 hi/lo splits ----------
__global__ void k_logmap_x(const float* __restrict__ x) {
    int warp = (blockIdx.x * blockDim.x + threadIdx.x) >> 5;
    int lane = threadIdx.x & 31;
    if (warp >= NN) return;
    const float* xr = x + (size_t)warp * 257;
    float v[8];
    float ss = 0.0f;
#pragma unroll
    for (int i = 0; i < 8; i++) {
        v[i] = xr[1 + lane * 8 + i];
        ss += v[i] * v[i];
    }
    ss = warp_sum(ss);
    float x0 = fmaxf(xr[0], 1.0f + EPSV);
    float sc = acoshf(x0) / fmaxf(sqrtf(ss), EPSV);
    ushort4 hi, lo;
#pragma unroll
    for (int i = 0; i < 8; i += 4) {
        float a0 = sc * v[i], a1 = sc * v[i + 1], a2 = sc * v[i + 2], a3 = sc * v[i + 3];
        __nv_bfloat16 h0 = __float2bfloat16(a0), h1 = __float2bfloat16(a1);
        __nv_bfloat16 h2 = __float2bfloat16(a2), h3 = __float2bfloat16(a3);
        hi.x = *(uint16_t*)&h0; hi.y = *(uint16_t*)&h1; hi.z = *(uint16_t*)&h2; hi.w = *(uint16_t*)&h3;
        __nv_bfloat16 l0 = __float2bfloat16(a0 - __bfloat162float(h0));
        __nv_bfloat16 l1 = __float2bfloat16(a1 - __bfloat162float(h1));
        __nv_bfloat16 l2 = __float2bfloat16(a2 - __bfloat162float(h2));
        __nv_bfloat16 l3 = __float2bfloat16(a3 - __bfloat162float(h3));
        lo.x = *(uint16_t*)&l0; lo.y = *(uint16_t*)&l1; lo.z = *(uint16_t*)&l2; lo.w = *(uint16_t*)&l3;
        *(ushort4*)&g_Uhi[warp * FTIN + lane * 8 + i] = hi;
        *(ushort4*)&g_Ulo[warp * FTIN + lane * 8 + i] = lo;
    }
}

// ------- weight prep: bf16 hi/lo split + transpose W[K][128] -> [n][k] --------
__global__ void k_prepW(const float* __restrict__ W, uint16_t* __restrict__ hiT,
                        uint16_t* __restrict__ loT, int K) {
    int idx = blockIdx.x * 256 + threadIdx.x;
    if (idx < K * 128) {
        int k = idx >> 7, n = idx & 127;
        float w = W[idx];
        __nv_bfloat16 h = __float2bfloat16(w);
        __nv_bfloat16 l = __float2bfloat16(w - __bfloat162float(h));
        hiT[n * K + k] = *(uint16_t*)&h;
        loT[n * K + k] = *(uint16_t*)&l;
    }
}

// ------ 3x bf16 tensor-core GEMM (m16n8k16), double-buffered mainloop ---------
template <int K>
__global__ void __launch_bounds__(256) k_gemm_tc(
    const uint16_t* __restrict__ Ahi, const uint16_t* __restrict__ Alo,
    const uint16_t* __restrict__ BhiT, const uint16_t* __restrict__ BloT,
    const float* __restrict__ bias, const float* __restrict__ a_src,
    const float* __restrict__ a_dst, __half* __restrict__ C) {
    __shared__ uint32_t AsH[2][1280], AsL[2][1280], BsH[2][1280], BsL[2][1280];
    __shared__ float sS[4][128], sD[4][128];
#define WIX(r, c) ((r) * 10 + (c))

    const int tid = threadIdx.x;
    const int lane = tid & 31;
    const int g = lane >> 2, q = lane & 3;
    const int wid = tid >> 5;
    const int wm = (wid >> 2) * 64;
    const int wn = (wid & 3) * 32;
    float d[4][4][4];
#pragma unroll
    for (int i = 0; i < 4; i++)
#pragma unroll
        for (int j = 0; j < 4; j++)
#pragma unroll
            for (int r = 0; r < 4; r++) d[i][j][r] = 0.0f;

    const int lr = tid >> 1;
    const int lc = (tid & 1) * 8;
    const size_t arow = (size_t)(blockIdx.x * 128 + lr) * K;

    uint4 ahv, alv, bhv, blv;
    auto load_chunk = [&](int kk) {
        ahv = *(const uint4*)&Ahi[arow + kk + lc];
        alv = *(const uint4*)&Alo[arow + kk + lc];
        bhv = *(const uint4*)&BhiT[lr * K + kk + lc];
        blv = *(const uint4*)&BloT[lr * K + kk + lc];
    };
    auto store_chunk = [&](int buf) {
        int w0 = lc >> 1;
        AsH[buf][WIX(lr, w0 + 0)] = ahv.x; AsH[buf][WIX(lr, w0 + 1)] = ahv.y;
        AsH[buf][WIX(lr, w0 + 2)] = ahv.z; AsH[buf][WIX(lr, w0 + 3)] = ahv.w;
        AsL[buf][WIX(lr, w0 + 0)] = alv.x; AsL[buf][WIX(lr, w0 + 1)] = alv.y;
        AsL[buf][WIX(lr, w0 + 2)] = alv.z; AsL[buf][WIX(lr, w0 + 3)] = alv.w;
        BsH[buf][WIX(lr, w0 + 0)] = bhv.x; BsH[buf][WIX(lr, w0 + 1)] = bhv.y;
        BsH[buf][WIX(lr, w0 + 2)] = bhv.z; BsH[buf][WIX(lr, w0 + 3)] = bhv.w;
        BsL[buf][WIX(lr, w0 + 0)] = blv.x; BsL[buf][WIX(lr, w0 + 1)] = blv.y;
        BsL[buf][WIX(lr, w0 + 2)] = blv.z; BsL[buf][WIX(lr, w0 + 3)] = blv.w;
    };
    auto mma_chunk = [&](int buf) {
        uint32_t bh[4][2], bl[4][2];
#pragma unroll
        for (int tn = 0; tn < 4; tn++) {
            int n = wn + tn * 8 + g;
            bh[tn][0] = BsH[buf][WIX(n, q)];
            bh[tn][1] = BsH[buf][WIX(n, q + 4)];
            bl[tn][0] = BsL[buf][WIX(n, q)];
            bl[tn][1] = BsL[buf][WIX(n, q + 4)];
        }
#pragma unroll
        for (int tm = 0; tm < 4; tm++) {
            int m = wm + tm * 16;
            uint32_t ah0 = AsH[buf][WIX(m + g, q)];
            uint32_t ah1 = AsH[buf][WIX(m + g + 8, q)];
            uint32_t ah2 = AsH[buf][WIX(m + g, q + 4)];
            uint32_t ah3 = AsH[buf][WIX(m + g + 8, q + 4)];
            uint32_t al0 = AsL[buf][WIX(m + g, q)];
            uint32_t al1 = AsL[buf][WIX(m + g + 8, q)];
            uint32_t al2 = AsL[buf][WIX(m + g, q + 4)];
            uint32_t al3 = AsL[buf][WIX(m + g + 8, q + 4)];
#pragma unroll
            for (int tn = 0; tn < 4; tn++) {
                mma_bf16(d[tm][tn], ah0, ah1, ah2, ah3, bh[tn][0], bh[tn][1]);
                mma_bf16(d[tm][tn], ah0, ah1, ah2, ah3, bl[tn][0], bl[tn][1]);
                mma_bf16(d[tm][tn], al0, al1, al2, al3, bh[tn][0], bh[tn][1]);
            }
        }
    };

    load_chunk(0);
    store_chunk(0);
    __syncthreads();
    int buf = 0;
    for (int kk = 16; kk < K; kk += 16) {
        load_chunk(kk);
        mma_chunk(buf);
        store_chunk(buf ^ 1);
        __syncthreads();
        buf ^= 1;
    }
    mma_chunk(buf);

    float ps0[4] = {0, 0, 0, 0}, ps1[4] = {0, 0, 0, 0};
    float pd0[4] = {0, 0, 0, 0}, pd1[4] = {0, 0, 0, 0};
#pragma unroll
    for (int tn = 0; tn < 4; tn++) {
        int col = wn + tn * 8 + 2 * q;
        float b0 = bias[col], b1 = bias[col + 1];
        float as0 = a_src[col], as1 = a_src[col + 1];
        float ad0 = a_dst[col], ad1 = a_dst[col + 1];
#pragma unroll
        for (int tm = 0; tm < 4; tm++) {
            int row0 = wm + tm * 16 + g;
            float v0 = d[tm][tn][0] + b0;
            float v1 = d[tm][tn][1] + b1;
            float v2 = d[tm][tn][2] + b0;
            float v3 = d[tm][tn][3] + b1;
            size_t rb = (size_t)(blockIdx.x * 128 + row0) * 128 + col;
            *(__half2*)&C[rb] = __floats2half2_rn(v0, v1);
            *(__half2*)&C[rb + 8 * 128] = __floats2half2_rn(v2, v3);
            ps0[tm] += v0 * as0 + v1 * as1;
            ps1[tm] += v2 * as0 + v3 * as1;
            pd0[tm] += v0 * ad0 + v1 * ad1;
            pd1[tm] += v2 * ad0 + v3 * ad1;
        }
    }
#pragma unroll
    for (int tm = 0; tm < 4; tm++) {
#pragma unroll
        for (int o = 1; o <= 2; o <<= 1) {
            ps0[tm] += __shfl_xor_sync(0xffffffffu, ps0[tm], o);
            ps1[tm] += __shfl_xor_sync(0xffffffffu, ps1[tm], o);
            pd0[tm] += __shfl_xor_sync(0xffffffffu, pd0[tm], o);
            pd1[tm] += __shfl_xor_sync(0xffffffffu, pd1[tm], o);
        }
        if (q == 0) {
            int row0 = wm + tm * 16 + g;
            int wnIdx = wid & 3;
            sS[wnIdx][row0] = ps0[tm]; sS[wnIdx][row0 + 8] = ps1[tm];
            sD[wnIdx][row0] = pd0[tm]; sD[wnIdx][row0 + 8] = pd1[tm];
        }
    }
    __syncthreads();
    if (tid < 128) {
        float s = sS[0][tid] + sS[1][tid] + sS[2][tid] + sS[3][tid];
        float dd = sD[0][tid] + sD[1][tid] + sD[2][tid] + sD[3][tid];
        g_ssrc[blockIdx.x * 128 + tid] = s;
        g_sdst[blockIdx.x * 128 + tid] = dd;
    }
#undef WIX
}

// ---------------- GAT aggregation fused with pointwise chain -------------------
// Pass 1 caches (src, ssrc) in registers (deg<=128 fast path); pass 2 gets them
// via __shfl — no second L2 round trip. z rows fp16 (256B), 4-wide z-load MLP.
template <int MODE>
__global__ void k_gat() {
    int warp = (blockIdx.x * blockDim.x + threadIdx.x) >> 5;
    int lane = threadIdx.x & 31;
    if (warp >= NN) return;
    int rs = g_rowstart[warp];
    int re = g_rowstart[warp + 1];
    int deg = re - rs;
    float sd = g_sdst[warp];
    const uint2* zh = (const uint2*)g_Zh;
    float4 a = make_float4(0.f, 0.f, 0.f, 0.f);
    float den = 0.0f;

    if (deg <= 128) {
        // pass 1: lane-parallel load of (s, q); max via lrelu monotonicity
        int sreg[4];
        float qreg[4];
        float qmax = -3.4e38f;
#pragma unroll
        for (int t = 0; t < 4; t++) {
            int e = t * 32 + lane;
            int ok = e < deg;
            int s = ok ? g_csrsrc[rs + e] : 0;
            float qq = ok ? g_ssrc[s] : -3.4e38f;
            sreg[t] = s;
            qreg[t] = qq;
            qmax = fmaxf(qmax, qq);
        }
        qmax = warp_max(qmax);
        float mx = lrelu02(sd + qmax);
        // pass 2: shfl-broadcast cached values; 4 z-loads in flight
#pragma unroll
        for (int t = 0; t < 4; t++) {
            int cnt = deg - t * 32;
            cnt = cnt > 32 ? 32 : cnt;
            if (cnt > 0) {
                int o = 0;
                for (; o + 4 <= cnt; o += 4) {
                    int sA = __shfl_sync(0xffffffffu, sreg[t], o + 0);
                    int sB = __shfl_sync(0xffffffffu, sreg[t], o + 1);
                    int sC = __shfl_sync(0xffffffffu, sreg[t], o + 2);
                    int sD_ = __shfl_sync(0xffffffffu, sreg[t], o + 3);
                    float qA = __shfl_sync(0xffffffffu, qreg[t], o + 0);
                    float qB = __shfl_sync(0xffffffffu, qreg[t], o + 1);
                    float qC = __shfl_sync(0xffffffffu, qreg[t], o + 2);
                    float qD = __shfl_sync(0xffffffffu, qreg[t], o + 3);
                    uint2 zA = zh[sA * 32 + lane];
                    uint2 zB = zh[sB * 32 + lane];
                    uint2 zC = zh[sC * 32 + lane];
                    uint2 zD = zh[sD_ * 32 + lane];
                    float wA = expf(lrelu02(sd + qA) - mx);
                    float wB = expf(lrelu02(sd + qB) - mx);
                    float wC = expf(lrelu02(sd + qC) - mx);
                    float wD = expf(lrelu02(sd + qD) - mx);
                    den += (wA + wB) + (wC + wD);
                    float2 fA0 = __half22float2(*reinterpret_cast<__half2*>(&zA.x));
                    float2 fA1 = __half22float2(*reinterpret_cast<__half2*>(&zA.y));
                    float2 fB0 = __half22float2(*reinterpret_cast<__half2*>(&zB.x));
                    float2 fB1 = __half22float2(*reinterpret_cast<__half2*>(&zB.y));
                    float2 fC0 = __half22float2(*reinterpret_cast<__half2*>(&zC.x));
                    float2 fC1 = __half22float2(*reinterpret_cast<__half2*>(&zC.y));
                    float2 fD0 = __half22float2(*reinterpret_cast<__half2*>(&zD.x));
                    float2 fD1 = __half22float2(*reinterpret_cast<__half2*>(&zD.y));
                    a.x = fmaf(wA, fA0.x, fmaf(wB, fB0.x, fmaf(wC, fC0.x, fmaf(wD, fD0.x, a.x))));
                    a.y = fmaf(wA, fA0.y, fmaf(wB, fB0.y, fmaf(wC, fC0.y, fmaf(wD, fD0.y, a.y))));
                    a.z = fmaf(wA, fA1.x, fmaf(wB, fB1.x, fmaf(wC, fC1.x, fmaf(wD, fD1.x, a.z))));
                    a.w = fmaf(wA, fA1.y, fmaf(wB, fB1.y, fmaf(wC, fC1.y, fmaf(wD, fD1.y, a.w))));
                }
                for (; o < cnt; o++) {
                    int s = __shfl_sync(0xffffffffu, sreg[t], o);
                    float qq = __shfl_sync(0xffffffffu, qreg[t], o);
                    float w = expf(lrelu02(sd + qq) - mx);
                    den += w;
                    uint2 zr = zh[s * 32 + lane];
                    float2 f01 = __half22float2(*reinterpret_cast<__half2*>(&zr.x));
                    float2 f23 = __half22float2(*reinterpret_cast<__half2*>(&zr.y));
                    a.x = fmaf(w, f01.x, a.x);
                    a.y = fmaf(w, f01.y, a.y);
                    a.z = fmaf(w, f23.x, a.z);
                    a.w = fmaf(w, f23.y, a.w);
                }
            }
        }
    } else {
        // slow path (deg > 128): original two-pass gmem walk
        float mx = -3.4e38f;
        for (int j = rs + lane; j < re; j += 32) {
            float e = lrelu02(sd + g_ssrc[g_csrsrc[j]]);
            mx = fmaxf(mx, e);
        }
        mx = warp_max(mx);
        for (int j = rs; j < re; j++) {
            int s = g_csrsrc[j];
            float w = expf(lrelu02(sd + g_ssrc[s]) - mx);
            den += w;
            uint2 zr = zh[s * 32 + lane];
            float2 f01 = __half22float2(*reinterpret_cast<__half2*>(&zr.x));
            float2 f23 = __half22float2(*reinterpret_cast<__half2*>(&zr.y));
            a.x = fmaf(w, f01.x, a.x);
            a.y = fmaf(w, f01.y, a.y);
            a.z = fmaf(w, f23.x, a.z);
            a.w = fmaf(w, f23.y, a.w);
        }
    }
    float inv = 1.0f / fmaxf(den, EPSV);
    a.x *= inv; a.y *= inv; a.z *= inv; a.w *= inv;

    float n2 = warp_sum(a.x * a.x + a.y * a.y + a.z * a.z + a.w * a.w);
    float n1 = sqrtf(n2);
    float ns = fmaxf(n1, EPSV);
    float coef = (n1 < EPSV) ? 1.0f : sinhf(ns) / ns;
    float4 hs;
    hs.x = coef * a.x; hs.y = coef * a.y; hs.z = coef * a.z; hs.w = coef * a.w;
    float hn2 = warp_sum(hs.x * hs.x + hs.y * hs.y + hs.z * hs.z + hs.w * hs.w);
    float h0p = sqrtf(1.0f + hn2);

    if (MODE == 1) {
        float* out = g_H2 + (size_t)warp * 129;
        if (lane == 0) out[0] = h0p;
        out[1 + lane * 4 + 0] = hs.x;
        out[1 + lane * 4 + 1] = hs.y;
        out[1 + lane * 4 + 2] = hs.z;
        out[1 + lane * 4 + 3] = hs.w;
    } else {
        float sc = acoshf(fmaxf(h0p, 1.0f + EPSV)) / fmaxf(sqrtf(hn2), EPSV);
        float4 u;
        u.x = sc * hs.x; u.y = sc * hs.y; u.z = sc * hs.z; u.w = sc * hs.w;
        u.x = gelu_tanh(u.x); u.y = gelu_tanh(u.y); u.z = gelu_tanh(u.z); u.w = gelu_tanh(u.w);
        float m2 = warp_sum(u.x * u.x + u.y * u.y + u.z * u.z + u.w * u.w);
        float m1 = sqrtf(m2);
        float ms = fmaxf(m1, EPSV);
        float coef2 = (m1 < EPSV) ? 1.0f : sinhf(ms) / ms;
        float4 h2;
        h2.x = coef2 * u.x; h2.y = coef2 * u.y; h2.z = coef2 * u.z; h2.w = coef2 * u.w;
        float q2 = warp_sum(h2.x * h2.x + h2.y * h2.y + h2.z * h2.z + h2.w * h2.w);
        float t0 = sqrtf(1.0f + q2);
        float sc2 = acoshf(fmaxf(t0, 1.0f + EPSV)) / fmaxf(sqrtf(q2), EPSV);
        float o0 = sc2 * h2.x, o1 = sc2 * h2.y, o2 = sc2 * h2.z, o3 = sc2 * h2.w;
        __nv_bfloat16 h0b = __float2bfloat16(o0), h1b = __float2bfloat16(o1);
        __nv_bfloat16 h2b = __float2bfloat16(o2), h3b = __float2bfloat16(o3);
        ushort4 hi, lo;
        hi.x = *(uint16_t*)&h0b; hi.y = *(uint16_t*)&h1b;
        hi.z = *(uint16_t*)&h2b; hi.w = *(uint16_t*)&h3b;
        __nv_bfloat16 l0 = __float2bfloat16(o0 - __bfloat162float(h0b));
        __nv_bfloat16 l1 = __float2bfloat16(o1 - __bfloat162float(h1b));
        __nv_bfloat16 l2 = __float2bfloat16(o2 - __bfloat162float(h2b));
        __nv_bfloat16 l3 = __float2bfloat16(o3 - __bfloat162float(h3b));
        lo.x = *(uint16_t*)&l0; lo.y = *(uint16_t*)&l1;
        lo.z = *(uint16_t*)&l2; lo.w = *(uint16_t*)&l3;
        *(ushort4*)&g_Uhi[warp * HID + lane * 4] = hi;
        *(ushort4*)&g_Ulo[warp * HID + lane * 4] = lo;
    }
}

// ---------------- graph head (2-phase) ----------------
// Phase A: 512 blocks; block (b,part) sums 64 rows x 129 dims -> g_part.
__global__ void k_headA() {
    int blk = blockIdx.x;
    int b = blk >> 3, part = blk & 7;
    int t = threadIdx.x;
    if (t < 129) {
        const float* base = g_H2 + ((size_t)(b * 512 + part * 64)) * 129;
        float s0 = 0.f, s1 = 0.f, s2 = 0.f, s3 = 0.f;
#pragma unroll 4
        for (int i = 0; i < 64; i += 4) {
            s0 += base[(i + 0) * 129 + t];
            s1 += base[(i + 1) * 129 + t];
            s2 += base[(i + 2) * 129 + t];
            s3 += base[(i + 3) * 129 + t];
        }
        g_part[blk * 129 + t] = (s0 + s1) + (s2 + s3);
    }
}
// Phase B: 64 blocks; combine 8 partials -> centroid; + projection head.
__global__ void k_headB(const float* __restrict__ Wlin, const float* __restrict__ lin_scale,
                        float* __restrict__ out) {
    int b = blockIdx.x;
    int t = threadIdx.x;
    __shared__ float ave[129];
    __shared__ float y[129];
    __shared__ float shv[2];
    const float* base = g_H2 + (size_t)b * 512 * 129;
    if (t < 129) {
        float s = 0.0f;
#pragma unroll
        for (int p = 0; p < 8; p++) s += g_part[(b * 8 + p) * 129 + t];
        ave[t] = s * (1.0f / 512.0f);
    }
    __syncthreads();
    if (t == 0) {
        float inner = 0.0f;
        for (int d = 1; d < 129; d++) inner += ave[d] * ave[d];
        inner -= ave[0] * ave[0];
        shv[0] = sqrtf(fmaxf(-inner, 1e-8f));
    }
    __syncthreads();
    if (t < 129) out[NB * 129 + b * 129 + t] = ave[t] / shv[0];
    if (t < 129) {
        float acc = 0.0f;
        for (int d = 0; d < 129; d++) acc = fmaf(base[d], Wlin[d * 129 + t], acc);
        y[t] = acc;
    }
    __syncthreads();
    if (t == 0) {
        float ss = 0.0f;
        for (int j = 1; j < 129; j++) ss += y[j] * y[j];
        float tim = 1.0f / (1.0f + expf(-y[0])) * lin_scale[0] + 1.1f;
        shv[1] = sqrtf((tim * tim - 1.0f) / fmaxf(ss, 1e-8f));
        out[b * 129] = tim;
    }
    __syncthreads();
    if (t >= 1 && t < 129) out[b * 129 + t] = y[t] * shv[1];
}

// ---------------- host-side symbol helpers + warmup ----------------
static float* sym_f(const void* s) { void* p = nullptr; cudaGetSymbolAddress(&p, s); return (float*)p; }
static uint16_t* sym_h(const void* s) { void* p = nullptr; cudaGetSymbolAddress(&p, s); return (uint16_t*)p; }
static __half* sym_hf(const void* s) { void* p = nullptr; cudaGetSymbolAddress(&p, s); return (__half*)p; }

namespace {
cudaStream_t g_side = 0;
cudaEvent_t g_evFork = 0, g_evJoin = 0, g_evW = 0;
bool g_haveSide = false;

struct Warmup {
    Warmup() {
        if (cudaStreamCreateWithFlags(&g_side, cudaStreamNonBlocking) == cudaSuccess &&
            cudaEventCreateWithFlags(&g_evFork, cudaEventDisableTiming) == cudaSuccess &&
            cudaEventCreateWithFlags(&g_evJoin, cudaEventDisableTiming) == cudaSuccess &&
            cudaEventCreateWithFlags(&g_evW, cudaEventDisableTiming) == cudaSuccess) {
            g_haveSide = true;
        }
        float* pH2 = sym_f(g_H2);
        __half* pZh = sym_hf(g_Zh);
        uint16_t* pUh = sym_h(g_Uhi);
        uint16_t* pUl = sym_h(g_Ulo);
        uint16_t* pW1h = sym_h(g_W1hiT);
        uint16_t* pW1l = sym_h(g_W1loT);
        float* pS  = sym_f(g_ssrc);
        if (!pH2 || !pZh || !pUh || !pUl || !pW1h || !pW1l || !pS) return;
        if (g_haveSide) {
            cudaEventRecord(g_evFork, 0);
            cudaStreamWaitEvent(g_side, g_evFork, 0);
            k_zero_cnt<<<1, 256, 0, g_side>>>();
            cudaEventRecord(g_evW, g_side);
            cudaStreamWaitEvent(0, g_evW, 0);
            cudaEventRecord(g_evJoin, g_side);
            cudaStreamWaitEvent(0, g_evJoin, 0);
        } else {
            k_zero_cnt<<<1, 256>>>();
        }
        k_hist<<<1, 256>>>((const int*)pH2, 256);
        k_scan<<<1, 1024>>>();
        k_scatter<<<1, 256>>>((const int*)pH2, 256);
        k_logmap_x<<<1, 256>>>(pH2);
        k_prepW<<<1, 256>>>(pH2, pW1h, pW1l, FTIN);
        k_gemm_tc<FTIN><<<1, 256>>>(pUh, pUl, pW1h, pW1l, pS, pS, pS, pZh);
        k_gemm_tc<HID><<<1, 256>>>(pUh, pUl, pW1h, pW1l, pS, pS, pS, pZh);
        k_gat<0><<<1, 256>>>();
        k_gat<1><<<1, 256>>>();
        k_headA<<<1, 256>>>();
        k_headB<<<1, 256>>>(pH2, pH2, pH2);
        cudaDeviceSynchronize();
        cudaGetLastError();
    }
};
static Warmup _warmup;
}

// ---------------- launch ----------------
extern "C" void kernel_launch(void* const* d_in, const int* in_sizes, int n_in,
                              void* d_out, int out_size) {
    const float* x  = (const float*)d_in[0];
    const int*   ei = (const int*)d_in[1];
    int p = (in_sizes[2] == 1) ? 3 : 2;
    const float* W1     = (const float*)d_in[p + 0];
    const float* b1     = (const float*)d_in[p + 1];
    const float* a1_src = (const float*)d_in[p + 2];
    const float* a1_dst = (const float*)d_in[p + 3];
    const float* W2     = (const float*)d_in[p + 4];
    const float* b2     = (const float*)d_in[p + 5];
    const float* a2_src = (const float*)d_in[p + 6];
    const float* a2_dst = (const float*)d_in[p + 7];
    const float* Wlin   = (const float*)d_in[p + 8];
    const float* lsc    = (const float*)d_in[p + 9];
    float* out = (float*)d_out;

    __half* pZh = sym_hf(g_Zh);
    uint16_t* pUh = sym_h(g_Uhi);
    uint16_t* pUl = sym_h(g_Ulo);
    uint16_t* pW1h = sym_h(g_W1hiT);
    uint16_t* pW1l = sym_h(g_W1loT);
    uint16_t* pW2h = sym_h(g_W2hiT);
    uint16_t* pW2l = sym_h(g_W2loT);

    // side stream: weight prep (joined before GEMM1) then CSR build (joined before gat0)
    if (g_haveSide) {
        cudaEventRecord(g_evFork, 0);
        cudaStreamWaitEvent(g_side, g_evFork, 0);
        k_prepW<<<(FTIN * 128 + 255) / 256, 256, 0, g_side>>>(W1, pW1h, pW1l, FTIN);
        k_prepW<<<(HID * 128 + 255) / 256, 256, 0, g_side>>>(W2, pW2h, pW2l, HID);
        cudaEventRecord(g_evW, g_side);
        k_zero_cnt<<<NN / 256, 256, 0, g_side>>>();
        k_hist<<<NE / 256, 256, 0, g_side>>>(ei, NE);
        k_scan<<<1, 1024, 0, g_side>>>();
        k_scatter<<<NE / 256, 256, 0, g_side>>>(ei, NE);
        cudaEventRecord(g_evJoin, g_side);
    } else {
        k_prepW<<<(FTIN * 128 + 255) / 256, 256>>>(W1, pW1h, pW1l, FTIN);
        k_prepW<<<(HID * 128 + 255) / 256, 256>>>(W2, pW2h, pW2l, HID);
        k_zero_cnt<<<NN / 256, 256>>>();
        k_hist<<<NE / 256, 256>>>(ei, NE);
        k_scan<<<1, 1024>>>();
        k_scatter<<<NE / 256, 256>>>(ei, NE);
    }

    // layer 1 (logmap overlaps prepW + CSR build)
    k_logmap_x<<<NN / 8, 256>>>(x);
    if (g_haveSide) cudaStreamWaitEvent(0, g_evW, 0);
    k_gemm_tc<FTIN><<<NN / 128, 256>>>(pUh, pUl, pW1h, pW1l, b1, a1_src, a1_dst, pZh);
    if (g_haveSide) cudaStreamWaitEvent(0, g_evJoin, 0);
    k_gat<0><<<NN / 8, 256>>>();

    // layer 2 (U2 in g_Uhi/g_Ulo, pitch HID)
    k_gemm_tc<HID><<<NN / 128, 256>>>(pUh, pUl, pW2h, pW2l, b2, a2_src, a2_dst, pZh);
    k_gat<1><<<NN / 8, 256>>>();

    // graph head
    k_headA<<<512, 256>>>();
    k_headB<<<NB, 256>>>(Wlin, lsc, out);
    (void)n_in; (void)out_size;
}